// round 10
// baseline (speedup 1.0000x reference)
#include <cuda_runtime.h>
#include <cuda_bf16.h>
#include <math.h>
#include <stdint.h>

#define Lc 4
#define Bc 4
#define Nc 2048
#define Dc 512
#define Hc 8
#define HDc 64
#define Mrows (Bc*Nc)   // 8192
#define DD (Dc*Dc)

// ---------------- scratch ----------------
__device__ __nv_bfloat16 g_wt[6*Lc*DD];            // transposed bf16 weights [n][k]
__device__ __nv_bfloat16 g_yb[Mrows*Dc];           // bf16 LN out
__device__ __nv_bfloat16 g_tb[Mrows*Dc];           // bf16 FF hidden
__device__ __nv_bfloat16 g_ob[Mrows*Dc];           // bf16 attention out
__device__ __nv_bfloat16 g_qb[Mrows*Dc];           // Q (pre-scaled, bf16)
__device__ __nv_bfloat16 g_kb[Mrows*Dc];           // K bf16
__device__ __nv_bfloat16 g_vt[Mrows*Dc];           // V bf16, per-(b,h) transposed [64][2048]

__device__ __forceinline__ float gelu_exact(float x) {
    return 0.5f * x * (1.0f + erff(x * 0.70710678118654752f));
}
__device__ __forceinline__ float ex2(float x) {
    float r;
    asm("ex2.approx.f32 %0, %1;" : "=f"(r) : "f"(x));
    return r;
}
__device__ __forceinline__ void cpasync16(void* sdst, const void* gsrc) {
    uint32_t s = (uint32_t)__cvta_generic_to_shared(sdst);
    asm volatile("cp.async.cg.shared.global [%0], [%1], 16;" :: "r"(s), "l"(gsrc));
}
__device__ __forceinline__ void mma_bf16(float* d, const uint32_t* a, const uint32_t* b) {
    asm volatile("mma.sync.aligned.m16n8k16.row.col.f32.bf16.bf16.f32 "
                 "{%0,%1,%2,%3}, {%4,%5,%6,%7}, {%8,%9}, {%0,%1,%2,%3};"
                 : "+f"(d[0]), "+f"(d[1]), "+f"(d[2]), "+f"(d[3])
                 : "r"(a[0]), "r"(a[1]), "r"(a[2]), "r"(a[3]), "r"(b[0]), "r"(b[1]));
}
__device__ __forceinline__ uint32_t packbf(float lo, float hi) {
    __nv_bfloat162 p = __floats2bfloat162_rn(lo, hi);
    return *(uint32_t*)&p;
}

// ---------------- prep: transpose [k][n] fp32 -> [n][k] bf16 ----------------
__global__ __launch_bounds__(256) void transpose_bf16(const float* __restrict__ in,
                                                      __nv_bfloat16* __restrict__ out) {
    __shared__ float t[32][33];
    const int l = blockIdx.z;
    const float* src = in + (long)l * DD;
    __nv_bfloat16* dst = out + (long)l * DD;
    const int n0 = blockIdx.x * 32, k0 = blockIdx.y * 32;
    const int tx = threadIdx.x & 31, ty = threadIdx.x >> 5;
    #pragma unroll
    for (int i = 0; i < 4; i++)
        t[ty + 8 * i][tx] = src[(long)(k0 + ty + 8 * i) * Dc + n0 + tx];
    __syncthreads();
    #pragma unroll
    for (int i = 0; i < 4; i++)
        dst[(long)(n0 + ty + 8 * i) * Dc + k0 + tx] = __float2bfloat16(t[tx][ty + 8 * i]);
}

// ---------------- LayerNorm -> bf16 ----------------
__global__ __launch_bounds__(128) void ln_kernel(const float* __restrict__ hin,
                                                 const float* __restrict__ gg,
                                                 const float* __restrict__ bb,
                                                 __nv_bfloat16* __restrict__ yout) {
    const int row = blockIdx.x;
    const int t = threadIdx.x;
    const float4 v = ((const float4*)(hin + (size_t)row * Dc))[t];
    float s  = v.x + v.y + v.z + v.w;
    float ss = v.x*v.x + v.y*v.y + v.z*v.z + v.w*v.w;
    #pragma unroll
    for (int o = 16; o > 0; o >>= 1) {
        s  += __shfl_xor_sync(0xFFFFFFFFu, s, o);
        ss += __shfl_xor_sync(0xFFFFFFFFu, ss, o);
    }
    __shared__ float sh[8];
    const int w = t >> 5;
    if ((t & 31) == 0) { sh[w] = s; sh[4 + w] = ss; }
    __syncthreads();
    const float st  = sh[0] + sh[1] + sh[2] + sh[3];
    const float sst = sh[4] + sh[5] + sh[6] + sh[7];
    const float mu  = st * (1.0f / Dc);
    const float var = sst * (1.0f / Dc) - mu * mu;
    const float inv = rsqrtf(var + 1e-5f);
    const float4 g4 = ((const float4*)gg)[t];
    const float4 b4 = ((const float4*)bb)[t];
    uint2 p;
    p.x = packbf((v.x - mu) * inv * g4.x + b4.x, (v.y - mu) * inv * g4.y + b4.y);
    p.y = packbf((v.z - mu) * inv * g4.z + b4.z, (v.w - mu) * inv * g4.w + b4.w);
    ((uint2*)(yout + (size_t)row * Dc))[t] = p;
}

struct GemmCtx { int lane, wid, wm, wn, m0, n0; };

// ================= bf16 GEMM mainloop (BM=128, BN=128, BK=32) =================
// A row-major [m][k] bf16, B pre-transposed [n][k] bf16 (both k-contiguous).
__device__ __forceinline__ void bf16_mainloop(const __nv_bfloat16* __restrict__ A,
                                              const __nv_bfloat16* __restrict__ Bt,
                                              uint32_t* smw, GemmCtx& cx,
                                              float acc[2][8][4]) {
    constexpr int RW = 20;  // words per smem row (32 bf16 + 8 pad)
    uint32_t* As = smw;                 // [2][128][20]
    uint32_t* Bs = smw + 2 * 128 * RW;  // [2][128][20]

    const int tid = threadIdx.x;
    cx.lane = tid & 31; cx.wid = tid >> 5;
    cx.wm = (cx.wid >> 1) * 32; cx.wn = (cx.wid & 1) * 64;
    cx.m0 = blockIdx.y * 128; cx.n0 = blockIdx.x * 128;

    #pragma unroll
    for (int mi = 0; mi < 2; mi++)
        #pragma unroll
        for (int ni = 0; ni < 8; ni++)
            #pragma unroll
            for (int j = 0; j < 4; j++) acc[mi][ni][j] = 0.0f;

    const int r0l = (tid) >> 2, ch0 = (tid & 3);
    const int r1l = (tid + 256) >> 2, ch1 = ((tid + 256) & 3);

    const __nv_bfloat16* Ag = A + (long)cx.m0 * Dc;
    const __nv_bfloat16* Bg = Bt + (long)cx.n0 * Dc;

    {
        cpasync16(&As[r0l * RW + ch0 * 4], Ag + (long)r0l * Dc + ch0 * 8);
        cpasync16(&As[r1l * RW + ch1 * 4], Ag + (long)r1l * Dc + ch1 * 8);
        cpasync16(&Bs[r0l * RW + ch0 * 4], Bg + (long)r0l * Dc + ch0 * 8);
        cpasync16(&Bs[r1l * RW + ch1 * 4], Bg + (long)r1l * Dc + ch1 * 8);
        asm volatile("cp.async.commit_group;");
    }

    const int KT = Dc / 32;
    for (int kt = 0; kt < KT; kt++) {
        const int st = kt & 1;
        if (kt + 1 < KT) {
            const int sn = st ^ 1;
            const int ko = (kt + 1) * 32;
            cpasync16(&As[sn * 128 * RW + r0l * RW + ch0 * 4], Ag + (long)r0l * Dc + ko + ch0 * 8);
            cpasync16(&As[sn * 128 * RW + r1l * RW + ch1 * 4], Ag + (long)r1l * Dc + ko + ch1 * 8);
            cpasync16(&Bs[sn * 128 * RW + r0l * RW + ch0 * 4], Bg + (long)r0l * Dc + ko + ch0 * 8);
            cpasync16(&Bs[sn * 128 * RW + r1l * RW + ch1 * 4], Bg + (long)r1l * Dc + ko + ch1 * 8);
            asm volatile("cp.async.commit_group;");
            asm volatile("cp.async.wait_group 1;");
        } else {
            asm volatile("cp.async.wait_group 0;");
        }
        __syncthreads();

        const uint32_t* A0 = As + st * 128 * RW;
        const uint32_t* B0 = Bs + st * 128 * RW;
        #pragma unroll
        for (int s = 0; s < 2; s++) {
            uint32_t af[2][4];
            #pragma unroll
            for (int mi = 0; mi < 2; mi++) {
                const int r = cx.wm + mi * 16 + (cx.lane >> 2);
                const int c = s * 8 + (cx.lane & 3);
                af[mi][0] = A0[r * RW + c];
                af[mi][1] = A0[(r + 8) * RW + c];
                af[mi][2] = A0[r * RW + c + 4];
                af[mi][3] = A0[(r + 8) * RW + c + 4];
            }
            uint32_t bf[8][2];
            #pragma unroll
            for (int ni = 0; ni < 8; ni++) {
                const int n = cx.wn + ni * 8 + (cx.lane >> 2);
                const int c = s * 8 + (cx.lane & 3);
                bf[ni][0] = B0[n * RW + c];
                bf[ni][1] = B0[n * RW + c + 4];
            }
            #pragma unroll
            for (int mi = 0; mi < 2; mi++)
                #pragma unroll
                for (int ni = 0; ni < 8; ni++)
                    mma_bf16(acc[mi][ni], af[mi], bf[ni]);
        }
        __syncthreads();
    }
}

// ---------------- QKV bf16 GEMM: z selects weight + output layout ----------------
#define QSC 0.06376237f  /* 512^-0.5 * log2(e) */
__global__ __launch_bounds__(256)
void qkv_gemm(const __nv_bfloat16* __restrict__ A, const __nv_bfloat16* __restrict__ wqt,
              const __nv_bfloat16* __restrict__ wkt, const __nv_bfloat16* __restrict__ wvt) {
    extern __shared__ uint32_t smw[];
    const int z = blockIdx.z;
    const __nv_bfloat16* W = (z == 0) ? wqt : (z == 1) ? wkt : wvt;
    GemmCtx cx;
    float acc[2][8][4];
    bf16_mainloop(A, W, smw, cx, acc);

    #pragma unroll
    for (int mi = 0; mi < 2; mi++) {
        const int r0 = cx.m0 + cx.wm + mi * 16 + (cx.lane >> 2);
        #pragma unroll
        for (int ni = 0; ni < 8; ni++) {
            const int col = cx.n0 + cx.wn + ni * 8 + (cx.lane & 3) * 2;
            #pragma unroll
            for (int half = 0; half < 2; half++) {
                const int r = r0 + half * 8;
                const float v0 = acc[mi][ni][half * 2 + 0];
                const float v1 = acc[mi][ni][half * 2 + 1];
                if (z == 0) {
                    *(uint32_t*)(g_qb + (long)r * Dc + col) = packbf(v0 * QSC, v1 * QSC);
                } else if (z == 1) {
                    *(uint32_t*)(g_kb + (long)r * Dc + col) = packbf(v0, v1);
                } else {
                    const int bidx = r >> 11, tok = r & 2047;
                    const long hb = ((long)bidx * Hc + (col >> 6)) * (HDc * Nc);
                    g_vt[hb + (long)(col & 63) * Nc + tok] = __float2bfloat16(v0);
                    g_vt[hb + (long)((col + 1) & 63) * Nc + tok] = __float2bfloat16(v1);
                }
            }
        }
    }
}

// ---------------- residual bf16 GEMM: C = resid + A@Wt + bias (fp32 out) ----------------
__global__ __launch_bounds__(256)
void resid_gemm(const __nv_bfloat16* __restrict__ A, const __nv_bfloat16* __restrict__ Wt,
                float* __restrict__ C, const float* __restrict__ bias,
                const float* __restrict__ resid) {
    extern __shared__ uint32_t smw[];
    GemmCtx cx;
    float acc[2][8][4];
    bf16_mainloop(A, Wt, smw, cx, acc);

    #pragma unroll
    for (int mi = 0; mi < 2; mi++) {
        const int r0 = cx.m0 + cx.wm + mi * 16 + (cx.lane >> 2);
        #pragma unroll
        for (int ni = 0; ni < 8; ni++) {
            const int col = cx.n0 + cx.wn + ni * 8 + (cx.lane & 3) * 2;
            #pragma unroll
            for (int half = 0; half < 2; half++) {
                const int r = r0 + half * 8;
                const float2 rs = *(const float2*)(resid + (long)r * Dc + col);
                float2 w2;
                w2.x = rs.x + acc[mi][ni][half * 2 + 0] + bias[col];
                w2.y = rs.y + acc[mi][ni][half * 2 + 1] + bias[col + 1];
                *(float2*)(C + (long)r * Dc + col) = w2;
            }
        }
    }
}

// ---------------- gelu bf16 GEMM: C = gelu(A@Wt + bias) (bf16 out) ----------------
__global__ __launch_bounds__(256)
void gelu_gemm(const __nv_bfloat16* __restrict__ A, const __nv_bfloat16* __restrict__ Wt,
               __nv_bfloat16* __restrict__ C, const float* __restrict__ bias) {
    extern __shared__ uint32_t smw[];
    GemmCtx cx;
    float acc[2][8][4];
    bf16_mainloop(A, Wt, smw, cx, acc);

    #pragma unroll
    for (int mi = 0; mi < 2; mi++) {
        const int r0 = cx.m0 + cx.wm + mi * 16 + (cx.lane >> 2);
        #pragma unroll
        for (int ni = 0; ni < 8; ni++) {
            const int col = cx.n0 + cx.wn + ni * 8 + (cx.lane & 3) * 2;
            #pragma unroll
            for (int half = 0; half < 2; half++) {
                const int r = r0 + half * 8;
                const float v0 = gelu_exact(acc[mi][ni][half * 2 + 0] + bias[col]);
                const float v1 = gelu_exact(acc[mi][ni][half * 2 + 1] + bias[col + 1]);
                *(uint32_t*)(C + (long)r * Dc + col) = packbf(v0, v1);
            }
        }
    }
}

// ---------------- bf16 fused flash attention ----------------
__global__ __launch_bounds__(256, 2) void fattn_kernel() {
    constexpr int QS = 72;
    extern __shared__ __align__(16) char smraw[];
    __nv_bfloat16* Qs = (__nv_bfloat16*)smraw;      // [128][72]
    __nv_bfloat16* Ks = Qs + 128 * QS;              // [2][64][72]
    __nv_bfloat16* Vt = Ks + 2 * 64 * QS;           // [2][64][72] (dim-major)

    const int qt = blockIdx.x, hh = blockIdx.y, bb = blockIdx.z;
    const int tid = threadIdx.x, lane = tid & 31, wid = tid >> 5;
    const long kvbase = ((long)bb * Nc) * Dc + hh * HDc;
    const long vtbase = ((long)bb * Hc + hh) * (HDc * Nc);

    #pragma unroll
    for (int i = 0; i < 4; i++) {
        const int idx = tid + 256 * i;
        const int r = idx >> 3, ch = idx & 7;
        cpasync16(&Qs[r * QS + ch * 8],
                  g_qb + kvbase + (long)(qt * 128 + r) * Dc + ch * 8);
    }
    #pragma unroll
    for (int i = 0; i < 2; i++) {
        const int idx = tid + 256 * i;
        const int r = idx >> 3, ch = idx & 7;
        cpasync16(&Ks[r * QS + ch * 8], g_kb + kvbase + (long)r * Dc + ch * 8);
        cpasync16(&Vt[r * QS + ch * 8], g_vt + vtbase + (long)r * Nc + ch * 8);
    }
    asm volatile("cp.async.commit_group;");
    asm volatile("cp.async.wait_group 0;");
    __syncthreads();

    uint32_t qf[4][4];
    {
        const uint32_t* Qw = (const uint32_t*)Qs;
        const int r0 = wid * 16 + (lane >> 2);
        #pragma unroll
        for (int ka = 0; ka < 4; ka++) {
            const int c = ka * 8 + (lane & 3);
            qf[ka][0] = Qw[r0 * 36 + c];
            qf[ka][1] = Qw[(r0 + 8) * 36 + c];
            qf[ka][2] = Qw[r0 * 36 + c + 4];
            qf[ka][3] = Qw[(r0 + 8) * 36 + c + 4];
        }
    }

    float o[8][4];
    #pragma unroll
    for (int d = 0; d < 8; d++)
        #pragma unroll
        for (int j = 0; j < 4; j++) o[d][j] = 0.0f;
    float m0 = -1e30f, m1 = -1e30f, l0 = 0.0f, l1 = 0.0f;

    for (int kt = 0; kt < Nc / 64; kt++) {
        const int st = kt & 1;
        if (kt + 1 < Nc / 64) {
            const int sn = st ^ 1;
            #pragma unroll
            for (int i = 0; i < 2; i++) {
                const int idx = tid + 256 * i;
                const int r = idx >> 3, ch = idx & 7;
                cpasync16(&Ks[sn * 64 * QS + r * QS + ch * 8],
                          g_kb + kvbase + (long)((kt + 1) * 64 + r) * Dc + ch * 8);
                cpasync16(&Vt[sn * 64 * QS + r * QS + ch * 8],
                          g_vt + vtbase + (long)r * Nc + (kt + 1) * 64 + ch * 8);
            }
            asm volatile("cp.async.commit_group;");
            asm volatile("cp.async.wait_group 1;");
        } else {
            asm volatile("cp.async.wait_group 0;");
        }
        __syncthreads();

        const uint32_t* Kw = (const uint32_t*)(Ks + st * 64 * QS);
        const uint32_t* Vw = (const uint32_t*)(Vt + st * 64 * QS);

        float sc[8][4];
        #pragma unroll
        for (int j = 0; j < 8; j++) {
            #pragma unroll
            for (int i = 0; i < 4; i++) sc[j][i] = 0.0f;
            const int n = j * 8 + (lane >> 2);
            #pragma unroll
            for (int ka = 0; ka < 4; ka++) {
                uint32_t b[2];
                b[0] = Kw[n * 36 + ka * 8 + (lane & 3)];
                b[1] = Kw[n * 36 + ka * 8 + 4 + (lane & 3)];
                mma_bf16(sc[j], qf[ka], b);
            }
        }

        float tm0 = -1e30f, tm1 = -1e30f;
        #pragma unroll
        for (int j = 0; j < 8; j++) {
            tm0 = fmaxf(tm0, fmaxf(sc[j][0], sc[j][1]));
            tm1 = fmaxf(tm1, fmaxf(sc[j][2], sc[j][3]));
        }
        tm0 = fmaxf(tm0, __shfl_xor_sync(0xFFFFFFFFu, tm0, 1));
        tm0 = fmaxf(tm0, __shfl_xor_sync(0xFFFFFFFFu, tm0, 2));
        tm1 = fmaxf(tm1, __shfl_xor_sync(0xFFFFFFFFu, tm1, 1));
        tm1 = fmaxf(tm1, __shfl_xor_sync(0xFFFFFFFFu, tm1, 2));
        const float nm0 = fmaxf(m0, tm0), nm1 = fmaxf(m1, tm1);
        const float c0 = ex2(m0 - nm0), c1 = ex2(m1 - nm1);
        m0 = nm0; m1 = nm1; l0 *= c0; l1 *= c1;
        #pragma unroll
        for (int j = 0; j < 8; j++) {
            sc[j][0] = ex2(sc[j][0] - m0);
            sc[j][1] = ex2(sc[j][1] - m0);
            sc[j][2] = ex2(sc[j][2] - m1);
            sc[j][3] = ex2(sc[j][3] - m1);
            l0 += sc[j][0] + sc[j][1];
            l1 += sc[j][2] + sc[j][3];
        }
        #pragma unroll
        for (int d = 0; d < 8; d++) {
            o[d][0] *= c0; o[d][1] *= c0; o[d][2] *= c1; o[d][3] *= c1;
        }

        #pragma unroll
        for (int s = 0; s < 4; s++) {
            uint32_t a[4];
            a[0] = packbf(sc[2 * s][0], sc[2 * s][1]);
            a[1] = packbf(sc[2 * s][2], sc[2 * s][3]);
            a[2] = packbf(sc[2 * s + 1][0], sc[2 * s + 1][1]);
            a[3] = packbf(sc[2 * s + 1][2], sc[2 * s + 1][3]);
            #pragma unroll
            for (int d = 0; d < 8; d++) {
                const int col = d * 8 + (lane >> 2);
                uint32_t b[2];
                b[0] = Vw[col * 36 + s * 8 + (lane & 3)];
                b[1] = Vw[col * 36 + s * 8 + 4 + (lane & 3)];
                mma_bf16(o[d], a, b);
            }
        }
        __syncthreads();
    }

    l0 += __shfl_xor_sync(0xFFFFFFFFu, l0, 1);
    l0 += __shfl_xor_sync(0xFFFFFFFFu, l0, 2);
    l1 += __shfl_xor_sync(0xFFFFFFFFu, l1, 1);
    l1 += __shfl_xor_sync(0xFFFFFFFFu, l1, 2);
    const float i0 = 1.0f / l0, i1 = 1.0f / l1;

    const int r0 = qt * 128 + wid * 16 + (lane >> 2);
    __nv_bfloat16* op0 = g_ob + ((long)bb * Nc) * Dc + hh * HDc + (long)r0 * Dc;
    __nv_bfloat16* op1 = op0 + 8 * Dc;
    #pragma unroll
    for (int d = 0; d < 8; d++) {
        const int col = d * 8 + 2 * (lane & 3);
        *(uint32_t*)(op0 + col) = packbf(o[d][0] * i0, o[d][1] * i0);
        *(uint32_t*)(op1 + col) = packbf(o[d][2] * i1, o[d][3] * i1);
    }
}

// ---------------- driver ----------------
extern "C" void kernel_launch(void* const* d_in, const int* in_sizes, int n_in,
                              void* d_out, int out_size) {
    const float* x    = (const float*)d_in[0];
    const float* Wq   = (const float*)d_in[1];
    const float* Wk   = (const float*)d_in[2];
    const float* Wv   = (const float*)d_in[3];
    const float* Wo   = (const float*)d_in[4];
    const float* bo   = (const float*)d_in[5];
    const float* ln1g = (const float*)d_in[6];
    const float* ln1b = (const float*)d_in[7];
    const float* W1   = (const float*)d_in[8];
    const float* b1   = (const float*)d_in[9];
    const float* W2   = (const float*)d_in[10];
    const float* b2   = (const float*)d_in[11];
    const float* ln2g = (const float*)d_in[12];
    const float* ln2b = (const float*)d_in[13];
    float* h = (float*)d_out;

    __nv_bfloat16 *pwt, *pyb, *ptb, *pob;
    cudaGetSymbolAddress((void**)&pwt, g_wt);
    cudaGetSymbolAddress((void**)&pyb, g_yb);
    cudaGetSymbolAddress((void**)&ptb, g_tb);
    cudaGetSymbolAddress((void**)&pob, g_ob);

    const int smemBF   = 4 * 128 * 20 * 4;                   // 40960
    const int smemAttn = (128 * 72 + 4 * 64 * 72) * 2;       // 55296
    cudaFuncSetAttribute(fattn_kernel, cudaFuncAttributeMaxDynamicSharedMemorySize, smemAttn);

    cudaMemcpyAsync(h, x, sizeof(float) * (size_t)Mrows * Dc, cudaMemcpyDeviceToDevice);

    // prep: transpose all weights to bf16 [n][k]
    const int WSZ = Lc * DD;
    const dim3 gT(Dc / 32, Dc / 32, Lc);
    transpose_bf16<<<gT, 256>>>(Wq, pwt + 0L * WSZ);
    transpose_bf16<<<gT, 256>>>(Wk, pwt + 1L * WSZ);
    transpose_bf16<<<gT, 256>>>(Wv, pwt + 2L * WSZ);
    transpose_bf16<<<gT, 256>>>(Wo, pwt + 3L * WSZ);
    transpose_bf16<<<gT, 256>>>(W1, pwt + 4L * WSZ);
    transpose_bf16<<<gT, 256>>>(W2, pwt + 5L * WSZ);

    const dim3 gProj(Dc / 128, Mrows / 128, 1);     // (4, 64)
    const dim3 gQKV(Dc / 128, Mrows / 128, 3);      // (4, 64, 3)
    const dim3 gAttn(Nc / 128, Hc, Bc);             // (16, 8, 4)

    for (int l = 0; l < Lc; l++) {
        const __nv_bfloat16* wqt = pwt + 0L * WSZ + (long)l * DD;
        const __nv_bfloat16* wkt = pwt + 1L * WSZ + (long)l * DD;
        const __nv_bfloat16* wvt = pwt + 2L * WSZ + (long)l * DD;
        const __nv_bfloat16* wot = pwt + 3L * WSZ + (long)l * DD;
        const __nv_bfloat16* w1t = pwt + 4L * WSZ + (long)l * DD;
        const __nv_bfloat16* w2t = pwt + 5L * WSZ + (long)l * DD;

        ln_kernel<<<Mrows, 128>>>(h, ln1g + l * Dc, ln1b + l * Dc, pyb);
        qkv_gemm<<<gQKV, 256, smemBF>>>(pyb, wqt, wkt, wvt);
        fattn_kernel<<<gAttn, 256, smemAttn>>>();
        resid_gemm<<<gProj, 256, smemBF>>>(pob, wot, h, bo + l * Dc, h);
        ln_kernel<<<Mrows, 128>>>(h, ln2g + l * Dc, ln2b + l * Dc, pyb);
        gelu_gemm<<<gProj, 256, smemBF>>>(pyb, w1t, ptb, b1 + l * Dc);
        resid_gemm<<<gProj, 256, smemBF>>>(ptb, w2t, h, b2 + l * Dc, h);
    }
}

// round 12
// speedup vs baseline: 1.0577x; 1.0577x over previous
#include <cuda_runtime.h>
#include <cuda_bf16.h>
#include <math.h>
#include <stdint.h>

#define Lc 4
#define Bc 4
#define Nc 2048
#define Dc 512
#define Hc 8
#define HDc 64
#define Mrows (Bc*Nc)   // 8192
#define DD (Dc*Dc)

// ---------------- scratch ----------------
__device__ __nv_bfloat16 g_wt[6*Lc*DD];            // transposed bf16 weights [n][k]
__device__ __nv_bfloat16 g_yb[Mrows*Dc];           // bf16 LN out
__device__ __nv_bfloat16 g_tb[Mrows*Dc];           // bf16 FF hidden
__device__ __nv_bfloat16 g_ob[Mrows*Dc];           // bf16 attention out
__device__ __nv_bfloat16 g_qb[Mrows*Dc];           // Q (pre-scaled, bf16)
__device__ __nv_bfloat16 g_kb[Mrows*Dc];           // K bf16
__device__ __nv_bfloat16 g_vt[Mrows*Dc];           // V bf16, per-(b,h) transposed [64][2048]

__device__ __forceinline__ float gelu_exact(float x) {
    return 0.5f * x * (1.0f + erff(x * 0.70710678118654752f));
}
__device__ __forceinline__ float ex2(float x) {
    float r;
    asm("ex2.approx.f32 %0, %1;" : "=f"(r) : "f"(x));
    return r;
}
__device__ __forceinline__ void cpasync16(void* sdst, const void* gsrc) {
    uint32_t s = (uint32_t)__cvta_generic_to_shared(sdst);
    asm volatile("cp.async.cg.shared.global [%0], [%1], 16;" :: "r"(s), "l"(gsrc));
}
__device__ __forceinline__ void mma_bf16(float* d, const uint32_t* a, const uint32_t* b) {
    asm volatile("mma.sync.aligned.m16n8k16.row.col.f32.bf16.bf16.f32 "
                 "{%0,%1,%2,%3}, {%4,%5,%6,%7}, {%8,%9}, {%0,%1,%2,%3};"
                 : "+f"(d[0]), "+f"(d[1]), "+f"(d[2]), "+f"(d[3])
                 : "r"(a[0]), "r"(a[1]), "r"(a[2]), "r"(a[3]), "r"(b[0]), "r"(b[1]));
}
__device__ __forceinline__ uint32_t packbf(float lo, float hi) {
    __nv_bfloat162 p = __floats2bfloat162_rn(lo, hi);
    return *(uint32_t*)&p;
}
__device__ __forceinline__ void ldm_x4(uint32_t& r0, uint32_t& r1, uint32_t& r2, uint32_t& r3,
                                       const uint32_t* p) {
    uint32_t a = (uint32_t)__cvta_generic_to_shared(p);
    asm volatile("ldmatrix.sync.aligned.m8n8.x4.shared.b16 {%0,%1,%2,%3}, [%4];"
                 : "=r"(r0), "=r"(r1), "=r"(r2), "=r"(r3) : "r"(a));
}

// ---------------- prep: transpose all 6 weight tensors [k][n] fp32 -> [n][k] bf16 ----------------
__global__ __launch_bounds__(256) void transpose_all(const float* __restrict__ Wq,
                                                     const float* __restrict__ Wk,
                                                     const float* __restrict__ Wv,
                                                     const float* __restrict__ Wo,
                                                     const float* __restrict__ W1,
                                                     const float* __restrict__ W2,
                                                     __nv_bfloat16* __restrict__ out) {
    __shared__ float t[32][33];
    const int z = blockIdx.z;            // 0..6*Lc-1
    const int w = z / Lc, l = z % Lc;
    const float* src = (w == 0 ? Wq : w == 1 ? Wk : w == 2 ? Wv :
                        w == 3 ? Wo : w == 4 ? W1 : W2) + (long)l * DD;
    __nv_bfloat16* dst = out + ((long)w * Lc + l) * DD;
    const int n0 = blockIdx.x * 32, k0 = blockIdx.y * 32;
    const int tx = threadIdx.x & 31, ty = threadIdx.x >> 5;
    #pragma unroll
    for (int i = 0; i < 4; i++)
        t[ty + 8 * i][tx] = src[(long)(k0 + ty + 8 * i) * Dc + n0 + tx];
    __syncthreads();
    #pragma unroll
    for (int i = 0; i < 4; i++)
        dst[(long)(n0 + ty + 8 * i) * Dc + k0 + tx] = __float2bfloat16(t[tx][ty + 8 * i]);
}

// ---------------- LayerNorm -> bf16 ----------------
__global__ __launch_bounds__(128) void ln_kernel(const float* __restrict__ hin,
                                                 const float* __restrict__ gg,
                                                 const float* __restrict__ bb,
                                                 __nv_bfloat16* __restrict__ yout) {
    const int row = blockIdx.x;
    const int t = threadIdx.x;
    const float4 v = ((const float4*)(hin + (size_t)row * Dc))[t];
    float s  = v.x + v.y + v.z + v.w;
    float ss = v.x*v.x + v.y*v.y + v.z*v.z + v.w*v.w;
    #pragma unroll
    for (int o = 16; o > 0; o >>= 1) {
        s  += __shfl_xor_sync(0xFFFFFFFFu, s, o);
        ss += __shfl_xor_sync(0xFFFFFFFFu, ss, o);
    }
    __shared__ float sh[8];
    const int w = t >> 5;
    if ((t & 31) == 0) { sh[w] = s; sh[4 + w] = ss; }
    __syncthreads();
    const float st  = sh[0] + sh[1] + sh[2] + sh[3];
    const float sst = sh[4] + sh[5] + sh[6] + sh[7];
    const float mu  = st * (1.0f / Dc);
    const float var = sst * (1.0f / Dc) - mu * mu;
    const float inv = rsqrtf(var + 1e-5f);
    const float4 g4 = ((const float4*)gg)[t];
    const float4 b4 = ((const float4*)bb)[t];
    uint2 p;
    p.x = packbf((v.x - mu) * inv * g4.x + b4.x, (v.y - mu) * inv * g4.y + b4.y);
    p.y = packbf((v.z - mu) * inv * g4.z + b4.z, (v.w - mu) * inv * g4.w + b4.w);
    ((uint2*)(yout + (size_t)row * Dc))[t] = p;
}

struct GemmCtx { int lane, wid, wm, wn, m0, n0; };

// ================= bf16 GEMM mainloop (BM=128, BN=128, BK=32), ldmatrix =================
__device__ __forceinline__ void bf16_mainloop(const __nv_bfloat16* __restrict__ A,
                                              const __nv_bfloat16* __restrict__ Bt,
                                              uint32_t* smw, GemmCtx& cx,
                                              float acc[2][8][4]) {
    constexpr int RW = 20;  // words per smem row (32 bf16 + 8 pad)
    uint32_t* As = smw;                 // [2][128][20]
    uint32_t* Bs = smw + 2 * 128 * RW;  // [2][128][20]

    const int tid = threadIdx.x;
    cx.lane = tid & 31; cx.wid = tid >> 5;
    cx.wm = (cx.wid >> 1) * 32; cx.wn = (cx.wid & 1) * 64;
    cx.m0 = blockIdx.y * 128; cx.n0 = blockIdx.x * 128;

    #pragma unroll
    for (int mi = 0; mi < 2; mi++)
        #pragma unroll
        for (int ni = 0; ni < 8; ni++)
            #pragma unroll
            for (int j = 0; j < 4; j++) acc[mi][ni][j] = 0.0f;

    const int r0l = (tid) >> 2, ch0 = (tid & 3);
    const int r1l = (tid + 256) >> 2, ch1 = ((tid + 256) & 3);

    const __nv_bfloat16* Ag = A + (long)cx.m0 * Dc;
    const __nv_bfloat16* Bg = Bt + (long)cx.n0 * Dc;

    {
        cpasync16(&As[r0l * RW + ch0 * 4], Ag + (long)r0l * Dc + ch0 * 8);
        cpasync16(&As[r1l * RW + ch1 * 4], Ag + (long)r1l * Dc + ch1 * 8);
        cpasync16(&Bs[r0l * RW + ch0 * 4], Bg + (long)r0l * Dc + ch0 * 8);
        cpasync16(&Bs[r1l * RW + ch1 * 4], Bg + (long)r1l * Dc + ch1 * 8);
        asm volatile("cp.async.commit_group;");
    }

    // ldmatrix lane addressing (precomputed)
    const int arow = (cx.lane & 15);            // A row within 16-row atom
    const int acw  = (cx.lane >> 4) * 4;        // A k-half word offset
    const int brow = ((cx.lane >> 4) << 3) + (cx.lane & 7);  // B row within 16-row pair
    const int bcw  = ((cx.lane >> 3) & 1) * 4;  // B k-half word offset

    const int KT = Dc / 32;
    for (int kt = 0; kt < KT; kt++) {
        const int st = kt & 1;
        if (kt + 1 < KT) {
            const int sn = st ^ 1;
            const int ko = (kt + 1) * 32;
            cpasync16(&As[sn * 128 * RW + r0l * RW + ch0 * 4], Ag + (long)r0l * Dc + ko + ch0 * 8);
            cpasync16(&As[sn * 128 * RW + r1l * RW + ch1 * 4], Ag + (long)r1l * Dc + ko + ch1 * 8);
            cpasync16(&Bs[sn * 128 * RW + r0l * RW + ch0 * 4], Bg + (long)r0l * Dc + ko + ch0 * 8);
            cpasync16(&Bs[sn * 128 * RW + r1l * RW + ch1 * 4], Bg + (long)r1l * Dc + ko + ch1 * 8);
            asm volatile("cp.async.commit_group;");
            asm volatile("cp.async.wait_group 1;");
        } else {
            asm volatile("cp.async.wait_group 0;");
        }
        __syncthreads();

        const uint32_t* A0 = As + st * 128 * RW;
        const uint32_t* B0 = Bs + st * 128 * RW;
        #pragma unroll
        for (int s = 0; s < 2; s++) {
            uint32_t af[2][4];
            #pragma unroll
            for (int mi = 0; mi < 2; mi++)
                ldm_x4(af[mi][0], af[mi][1], af[mi][2], af[mi][3],
                       &A0[(cx.wm + mi * 16 + arow) * RW + s * 8 + acw]);
            uint32_t bf[8][2];
            #pragma unroll
            for (int np = 0; np < 4; np++)
                ldm_x4(bf[2 * np][0], bf[2 * np][1], bf[2 * np + 1][0], bf[2 * np + 1][1],
                       &B0[(cx.wn + np * 16 + brow) * RW + s * 8 + bcw]);
            #pragma unroll
            for (int mi = 0; mi < 2; mi++)
                #pragma unroll
                for (int ni = 0; ni < 8; ni++)
                    mma_bf16(acc[mi][ni], af[mi], bf[ni]);
        }
        __syncthreads();
    }
}

// ---------------- QKV bf16 GEMM: z selects weight + output layout ----------------
#define QSC 0.06376237f  /* 512^-0.5 * log2(e) */
__global__ __launch_bounds__(256, 2)
void qkv_gemm(const __nv_bfloat16* __restrict__ A, const __nv_bfloat16* __restrict__ wqt,
              const __nv_bfloat16* __restrict__ wkt, const __nv_bfloat16* __restrict__ wvt) {
    extern __shared__ uint32_t smw[];
    const int z = blockIdx.z;
    const __nv_bfloat16* W = (z == 0) ? wqt : (z == 1) ? wkt : wvt;
    GemmCtx cx;
    float acc[2][8][4];
    bf16_mainloop(A, W, smw, cx, acc);

    #pragma unroll
    for (int mi = 0; mi < 2; mi++) {
        const int r0 = cx.m0 + cx.wm + mi * 16 + (cx.lane >> 2);
        #pragma unroll
        for (int ni = 0; ni < 8; ni++) {
            const int col = cx.n0 + cx.wn + ni * 8 + (cx.lane & 3) * 2;
            #pragma unroll
            for (int half = 0; half < 2; half++) {
                const int r = r0 + half * 8;
                const float v0 = acc[mi][ni][half * 2 + 0];
                const float v1 = acc[mi][ni][half * 2 + 1];
                if (z == 0) {
                    *(uint32_t*)(g_qb + (long)r * Dc + col) = packbf(v0 * QSC, v1 * QSC);
                } else if (z == 1) {
                    *(uint32_t*)(g_kb + (long)r * Dc + col) = packbf(v0, v1);
                } else {
                    const int bidx = r >> 11, tok = r & 2047;
                    const long hb = ((long)bidx * Hc + (col >> 6)) * (HDc * Nc);
                    g_vt[hb + (long)(col & 63) * Nc + tok] = __float2bfloat16(v0);
                    g_vt[hb + (long)((col + 1) & 63) * Nc + tok] = __float2bfloat16(v1);
                }
            }
        }
    }
}

// ---------------- residual bf16 GEMM: C = resid + A@Wt + bias (fp32 out) ----------------
__global__ __launch_bounds__(256, 2)
void resid_gemm(const __nv_bfloat16* __restrict__ A, const __nv_bfloat16* __restrict__ Wt,
                float* __restrict__ C, const float* __restrict__ bias,
                const float* __restrict__ resid) {
    extern __shared__ uint32_t smw[];
    GemmCtx cx;
    float acc[2][8][4];
    bf16_mainloop(A, Wt, smw, cx, acc);

    #pragma unroll
    for (int mi = 0; mi < 2; mi++) {
        const int r0 = cx.m0 + cx.wm + mi * 16 + (cx.lane >> 2);
        #pragma unroll
        for (int ni = 0; ni < 8; ni++) {
            const int col = cx.n0 + cx.wn + ni * 8 + (cx.lane & 3) * 2;
            #pragma unroll
            for (int half = 0; half < 2; half++) {
                const int r = r0 + half * 8;
                const float2 rs = *(const float2*)(resid + (long)r * Dc + col);
                float2 w2;
                w2.x = rs.x + acc[mi][ni][half * 2 + 0] + bias[col];
                w2.y = rs.y + acc[mi][ni][half * 2 + 1] + bias[col + 1];
                *(float2*)(C + (long)r * Dc + col) = w2;
            }
        }
    }
}

// ---------------- gelu bf16 GEMM: C = gelu(A@Wt + bias) (bf16 out) ----------------
__global__ __launch_bounds__(256, 2)
void gelu_gemm(const __nv_bfloat16* __restrict__ A, const __nv_bfloat16* __restrict__ Wt,
               __nv_bfloat16* __restrict__ C, const float* __restrict__ bias) {
    extern __shared__ uint32_t smw[];
    GemmCtx cx;
    float acc[2][8][4];
    bf16_mainloop(A, Wt, smw, cx, acc);

    #pragma unroll
    for (int mi = 0; mi < 2; mi++) {
        const int r0 = cx.m0 + cx.wm + mi * 16 + (cx.lane >> 2);
        #pragma unroll
        for (int ni = 0; ni < 8; ni++) {
            const int col = cx.n0 + cx.wn + ni * 8 + (cx.lane & 3) * 2;
            #pragma unroll
            for (int half = 0; half < 2; half++) {
                const int r = r0 + half * 8;
                const float v0 = gelu_exact(acc[mi][ni][half * 2 + 0] + bias[col]);
                const float v1 = gelu_exact(acc[mi][ni][half * 2 + 1] + bias[col + 1]);
                *(uint32_t*)(C + (long)r * Dc + col) = packbf(v0, v1);
            }
        }
    }
}

// ---------------- bf16 fused flash attention (ldmatrix fragments) ----------------
__global__ __launch_bounds__(256, 2) void fattn_kernel() {
    constexpr int QS = 72;
    extern __shared__ __align__(16) char smraw[];
    __nv_bfloat16* Qs = (__nv_bfloat16*)smraw;      // [128][72]
    __nv_bfloat16* Ks = Qs + 128 * QS;              // [2][64][72]
    __nv_bfloat16* Vt = Ks + 2 * 64 * QS;           // [2][64][72] (dim-major)

    const int qt = blockIdx.x, hh = blockIdx.y, bb = blockIdx.z;
    const int tid = threadIdx.x, lane = tid & 31, wid = tid >> 5;
    const long kvbase = ((long)bb * Nc) * Dc + hh * HDc;
    const long vtbase = ((long)bb * Hc + hh) * (HDc * Nc);

    #pragma unroll
    for (int i = 0; i < 4; i++) {
        const int idx = tid + 256 * i;
        const int r = idx >> 3, ch = idx & 7;
        cpasync16(&Qs[r * QS + ch * 8],
                  g_qb + kvbase + (long)(qt * 128 + r) * Dc + ch * 8);
    }
    #pragma unroll
    for (int i = 0; i < 2; i++) {
        const int idx = tid + 256 * i;
        const int r = idx >> 3, ch = idx & 7;
        cpasync16(&Ks[r * QS + ch * 8], g_kb + kvbase + (long)r * Dc + ch * 8);
        cpasync16(&Vt[r * QS + ch * 8], g_vt + vtbase + (long)r * Nc + ch * 8);
    }
    asm volatile("cp.async.commit_group;");
    asm volatile("cp.async.wait_group 0;");
    __syncthreads();

    // ldmatrix lane addressing
    const int arow = (lane & 15);
    const int acw  = (lane >> 4) * 4;
    const int brow = ((lane >> 4) << 3) + (lane & 7);
    const int bcw  = ((lane >> 3) & 1) * 4;

    uint32_t qf[4][4];
    {
        const uint32_t* Qw = (const uint32_t*)Qs;
        #pragma unroll
        for (int ka = 0; ka < 4; ka++)
            ldm_x4(qf[ka][0], qf[ka][1], qf[ka][2], qf[ka][3],
                   &Qw[(wid * 16 + arow) * 36 + ka * 8 + acw]);
    }

    float o[8][4];
    #pragma unroll
    for (int d = 0; d < 8; d++)
        #pragma unroll
        for (int j = 0; j < 4; j++) o[d][j] = 0.0f;
    float m0 = -1e30f, m1 = -1e30f, l0 = 0.0f, l1 = 0.0f;

    for (int kt = 0; kt < Nc / 64; kt++) {
        const int st = kt & 1;
        if (kt + 1 < Nc / 64) {
            const int sn = st ^ 1;
            #pragma unroll
            for (int i = 0; i < 2; i++) {
                const int idx = tid + 256 * i;
                const int r = idx >> 3, ch = idx & 7;
                cpasync16(&Ks[sn * 64 * QS + r * QS + ch * 8],
                          g_kb + kvbase + (long)((kt + 1) * 64 + r) * Dc + ch * 8);
                cpasync16(&Vt[sn * 64 * QS + r * QS + ch * 8],
                          g_vt + vtbase + (long)r * Nc + (kt + 1) * 64 + ch * 8);
            }
            asm volatile("cp.async.commit_group;");
            asm volatile("cp.async.wait_group 1;");
        } else {
            asm volatile("cp.async.wait_group 0;");
        }
        __syncthreads();

        const uint32_t* Kw = (const uint32_t*)(Ks + st * 64 * QS);
        const uint32_t* Vw = (const uint32_t*)(Vt + st * 64 * QS);

        // S = Q @ K^T
        float sc[8][4];
        #pragma unroll
        for (int j = 0; j < 8; j++)
            #pragma unroll
            for (int i = 0; i < 4; i++) sc[j][i] = 0.0f;
        #pragma unroll
        for (int jj = 0; jj < 4; jj++) {
            #pragma unroll
            for (int ka = 0; ka < 4; ka++) {
                uint32_t bA[2], bB[2];
                ldm_x4(bA[0], bA[1], bB[0], bB[1],
                       &Kw[(jj * 16 + brow) * 36 + ka * 8 + bcw]);
                mma_bf16(sc[2 * jj], qf[ka], bA);
                mma_bf16(sc[2 * jj + 1], qf[ka], bB);
            }
        }

        float tm0 = -1e30f, tm1 = -1e30f;
        #pragma unroll
        for (int j = 0; j < 8; j++) {
            tm0 = fmaxf(tm0, fmaxf(sc[j][0], sc[j][1]));
            tm1 = fmaxf(tm1, fmaxf(sc[j][2], sc[j][3]));
        }
        tm0 = fmaxf(tm0, __shfl_xor_sync(0xFFFFFFFFu, tm0, 1));
        tm0 = fmaxf(tm0, __shfl_xor_sync(0xFFFFFFFFu, tm0, 2));
        tm1 = fmaxf(tm1, __shfl_xor_sync(0xFFFFFFFFu, tm1, 1));
        tm1 = fmaxf(tm1, __shfl_xor_sync(0xFFFFFFFFu, tm1, 2));
        const float nm0 = fmaxf(m0, tm0), nm1 = fmaxf(m1, tm1);
        const float c0 = ex2(m0 - nm0), c1 = ex2(m1 - nm1);
        m0 = nm0; m1 = nm1; l0 *= c0; l1 *= c1;
        #pragma unroll
        for (int j = 0; j < 8; j++) {
            sc[j][0] = ex2(sc[j][0] - m0);
            sc[j][1] = ex2(sc[j][1] - m0);
            sc[j][2] = ex2(sc[j][2] - m1);
            sc[j][3] = ex2(sc[j][3] - m1);
            l0 += sc[j][0] + sc[j][1];
            l1 += sc[j][2] + sc[j][3];
        }
        #pragma unroll
        for (int d = 0; d < 8; d++) {
            o[d][0] *= c0; o[d][1] *= c0; o[d][2] *= c1; o[d][3] *= c1;
        }

        // O += P @ V
        #pragma unroll
        for (int s = 0; s < 4; s++) {
            uint32_t a[4];
            a[0] = packbf(sc[2 * s][0], sc[2 * s][1]);
            a[1] = packbf(sc[2 * s][2], sc[2 * s][3]);
            a[2] = packbf(sc[2 * s + 1][0], sc[2 * s + 1][1]);
            a[3] = packbf(sc[2 * s + 1][2], sc[2 * s + 1][3]);
            #pragma unroll
            for (int dp = 0; dp < 4; dp++) {
                uint32_t bA[2], bB[2];
                ldm_x4(bA[0], bA[1], bB[0], bB[1],
                       &Vw[(dp * 16 + brow) * 36 + s * 8 + bcw]);
                mma_bf16(o[2 * dp], a, bA);
                mma_bf16(o[2 * dp + 1], a, bB);
            }
        }
        __syncthreads();
    }

    l0 += __shfl_xor_sync(0xFFFFFFFFu, l0, 1);
    l0 += __shfl_xor_sync(0xFFFFFFFFu, l0, 2);
    l1 += __shfl_xor_sync(0xFFFFFFFFu, l1, 1);
    l1 += __shfl_xor_sync(0xFFFFFFFFu, l1, 2);
    const float i0 = 1.0f / l0, i1 = 1.0f / l1;

    const int r0 = qt * 128 + wid * 16 + (lane >> 2);
    __nv_bfloat16* op0 = g_ob + ((long)bb * Nc) * Dc + hh * HDc + (long)r0 * Dc;
    __nv_bfloat16* op1 = op0 + 8 * Dc;
    #pragma unroll
    for (int d = 0; d < 8; d++) {
        const int col = d * 8 + 2 * (lane & 3);
        *(uint32_t*)(op0 + col) = packbf(o[d][0] * i0, o[d][1] * i0);
        *(uint32_t*)(op1 + col) = packbf(o[d][2] * i1, o[d][3] * i1);
    }
}

// ---------------- driver ----------------
extern "C" void kernel_launch(void* const* d_in, const int* in_sizes, int n_in,
                              void* d_out, int out_size) {
    const float* x    = (const float*)d_in[0];
    const float* Wq   = (const float*)d_in[1];
    const float* Wk   = (const float*)d_in[2];
    const float* Wv   = (const float*)d_in[3];
    const float* Wo   = (const float*)d_in[4];
    const float* bo   = (const float*)d_in[5];
    const float* ln1g = (const float*)d_in[6];
    const float* ln1b = (const float*)d_in[7];
    const float* W1   = (const float*)d_in[8];
    const float* b1   = (const float*)d_in[9];
    const float* W2   = (const float*)d_in[10];
    const float* b2   = (const float*)d_in[11];
    const float* ln2g = (const float*)d_in[12];
    const float* ln2b = (const float*)d_in[13];
    float* h = (float*)d_out;

    __nv_bfloat16 *pwt, *pyb, *ptb, *pob;
    cudaGetSymbolAddress((void**)&pwt, g_wt);
    cudaGetSymbolAddress((void**)&pyb, g_yb);
    cudaGetSymbolAddress((void**)&ptb, g_tb);
    cudaGetSymbolAddress((void**)&pob, g_ob);

    const int smemBF   = 4 * 128 * 20 * 4;                   // 40960
    const int smemAttn = (128 * 72 + 4 * 64 * 72) * 2;       // 55296
    cudaFuncSetAttribute(fattn_kernel, cudaFuncAttributeMaxDynamicSharedMemorySize, smemAttn);

    cudaMemcpyAsync(h, x, sizeof(float) * (size_t)Mrows * Dc, cudaMemcpyDeviceToDevice);

    // prep: transpose all weights to bf16 [n][k] in ONE launch
    const int WSZ = Lc * DD;
    transpose_all<<<dim3(Dc / 32, Dc / 32, 6 * Lc), 256>>>(Wq, Wk, Wv, Wo, W1, W2, pwt);

    const dim3 gProj(Dc / 128, Mrows / 128, 1);     // (4, 64)
    const dim3 gQKV(Dc / 128, Mrows / 128, 3);      // (4, 64, 3)
    const dim3 gAttn(Nc / 128, Hc, Bc);             // (16, 8, 4)

    for (int l = 0; l < Lc; l++) {
        const __nv_bfloat16* wqt = pwt + 0L * WSZ + (long)l * DD;
        const __nv_bfloat16* wkt = pwt + 1L * WSZ + (long)l * DD;
        const __nv_bfloat16* wvt = pwt + 2L * WSZ + (long)l * DD;
        const __nv_bfloat16* wot = pwt + 3L * WSZ + (long)l * DD;
        const __nv_bfloat16* w1t = pwt + 4L * WSZ + (long)l * DD;
        const __nv_bfloat16* w2t = pwt + 5L * WSZ + (long)l * DD;

        ln_kernel<<<Mrows, 128>>>(h, ln1g + l * Dc, ln1b + l * Dc, pyb);
        qkv_gemm<<<gQKV, 256, smemBF>>>(pyb, wqt, wkt, wvt);
        fattn_kernel<<<gAttn, 256, smemAttn>>>();
        resid_gemm<<<gProj, 256, smemBF>>>(pob, wot, h, bo + l * Dc, h);
        ln_kernel<<<Mrows, 128>>>(h, ln2g + l * Dc, ln2b + l * Dc, pyb);
        gelu_gemm<<<gProj, 256, smemBF>>>(pyb, w1t, ptb, b1 + l * Dc);
        resid_gemm<<<gProj, 256, smemBF>>>(ptb, w2t, h, b2 + l * Dc, h);
    }
}